// round 1
// baseline (speedup 1.0000x reference)
#include <cuda_runtime.h>

#define NN 50000
#define EE 800000
#define INC 64
#define HID 128
#define NC1 64
#define NC2 16

#define NB3 148
#define PART_STRIDE 16385   // 64*256 pooled + 1 den

// ---------------- scratch (device globals; no allocation allowed) ----------------
__device__ __align__(256) float g_agg[NN * INC];
__device__ __align__(256) float g_x1[NN * HID];
__device__ __align__(256) float g_s[NN * NC1];
__device__ __align__(256) float g_As[NN * NC1];
__device__ __align__(256) float g_deg[NN];
__device__ __align__(256) float g_part[NB3 * PART_STRIDE];
__device__ __align__(256) float g_red[PART_STRIDE];
__device__ __align__(256) float g_M[NC1 * NC1];
__device__ __align__(256) float g_deg2[NC1];
__device__ __align__(256) float g_s2[NC1 * NC2];

// ---------------- helpers ----------------
__device__ __forceinline__ void red_add_v4(float* p, float4 v) {
    asm volatile("red.global.add.v4.f32 [%0], {%1,%2,%3,%4};"
                 :: "l"(p), "f"(v.x), "f"(v.y), "f"(v.z), "f"(v.w) : "memory");
}
__device__ __forceinline__ void red_add_f32(float* p, float v) {
    asm volatile("red.global.add.f32 [%0], %1;" :: "l"(p), "f"(v) : "memory");
}

// ---------------- K0: zero accumulators ----------------
__global__ void k_zero() {
    int i = blockIdx.x * blockDim.x + threadIdx.x;
    float4 z = make_float4(0.f, 0.f, 0.f, 0.f);
    if (i < NN * INC / 4) ((float4*)g_agg)[i] = z;
    if (i < NN * NC1 / 4) ((float4*)g_As)[i] = z;
    if (i < NN / 4)       ((float4*)g_deg)[i] = z;
}

// ---------------- K1: agg[col[e]] += drop_mask[row[e]] * x[row[e]] ----------------
__global__ void k_scatter_agg(const float* __restrict__ x,
                              const int* __restrict__ row,
                              const int* __restrict__ col,
                              const float* __restrict__ mask) {
    int t = blockIdx.x * blockDim.x + threadIdx.x;   // E*16 threads
    int e = t >> 4, c4 = t & 15;
    int r = __ldg(row + e);
    int c = __ldg(col + e);
    float m = __ldg(mask + r);
    float4 v = __ldg((const float4*)(x + (size_t)r * INC) + c4);
    v.x *= m; v.y *= m; v.z *= m; v.w *= m;
    red_add_v4(g_agg + (size_t)c * INC + c4 * 4, v);
}

// ---------------- K2b: A_s[row[e]] += s[col[e]]; deg[row[e]] += 1 ----------------
__global__ void k_scatter_As(const int* __restrict__ row,
                             const int* __restrict__ col) {
    int t = blockIdx.x * blockDim.x + threadIdx.x;   // E*16 threads
    int e = t >> 4, c4 = t & 15;
    int r = __ldg(row + e);
    int c = __ldg(col + e);
    float4 v = __ldg((const float4*)(g_s + (size_t)c * NC1) + c4);
    red_add_v4(g_As + (size_t)r * NC1 + c4 * 4, v);
    if (c4 == 0) red_add_f32(g_deg + r, 1.0f);
}

// ---------------- K2: per-node fused GraphConv+ReLU, pool-proj, LN, softmax/log_softmax ----------------
#define K2_THREADS 512
// smem floats: wrel_t 8192 | wroot_t 8192 | pw_t 8192 | b1 128 | pb1/g1/be1 3*64 | in 16*128 | x1 16*128
#define K2_SMEM_FLOATS (8192*3 + 128 + 192 + 2048 + 2048)

__global__ void k_node(const float* __restrict__ x, const float* __restrict__ mask,
                       const float* __restrict__ W1rel, const float* __restrict__ b1,
                       const float* __restrict__ W1root,
                       const float* __restrict__ pW1, const float* __restrict__ pb1,
                       const float* __restrict__ g1, const float* __restrict__ be1,
                       float* __restrict__ out) {
    extern __shared__ float sm[];
    float* wrel  = sm;
    float* wroot = wrel + 8192;
    float* pw    = wroot + 8192;
    float* b1s   = pw + 8192;
    float* pb1s  = b1s + 128;
    float* g1s   = pb1s + 64;
    float* be1s  = g1s + 64;
    float* ins   = be1s + 64;      // [16][128] : agg | xdrop
    float* x1sh  = ins + 2048;     // [16][128]

    int tid = threadIdx.x;
    for (int i = tid; i < 8192; i += K2_THREADS) {
        int j = i >> 6, k = i & 63;                 // W1* are [128][64]
        wrel[k * 128 + j]  = W1rel[i];
        wroot[k * 128 + j] = W1root[i];
    }
    for (int i = tid; i < 8192; i += K2_THREADS) {
        int j = i >> 7, k = i & 127;                // pW1 is [64][128]
        pw[k * 64 + j] = pW1[i];
    }
    if (tid < 128) b1s[tid] = b1[tid];
    if (tid < 64) { pb1s[tid] = pb1[tid]; g1s[tid] = g1[tid]; be1s[tid] = be1[tid]; }
    __syncthreads();

    int w = tid >> 5, lane = tid & 31;
    int per = (NN + gridDim.x - 1) / gridDim.x;
    int n0 = blockIdx.x * per;
    int n1 = min(n0 + per, NN);
    float* insw = ins + w * 128;
    float* x1w  = x1sh + w * 128;

    for (int n = n0 + w; n < n1; n += 16) {
        // stage agg (64) and x_drop (64)
        if (lane < 16) {
            ((float4*)insw)[lane] = *((const float4*)(g_agg + (size_t)n * 64) + lane);
        } else {
            int k4 = lane - 16;
            float m = __ldg(mask + n);
            float4 v = __ldg((const float4*)(x + (size_t)n * 64) + k4);
            v.x *= m; v.y *= m; v.z *= m; v.w *= m;
            ((float4*)insw)[16 + k4] = v;
        }
        __syncwarp();
        // x1[j] for j = 4*lane .. 4*lane+3
        float4 acc = ((float4*)b1s)[lane];
        #pragma unroll 8
        for (int k = 0; k < 64; k++) {
            float a  = insw[k];
            float xd = insw[64 + k];
            float4 w1 = ((float4*)(wrel + k * 128))[lane];
            float4 w2 = ((float4*)(wroot + k * 128))[lane];
            acc.x += a * w1.x + xd * w2.x;
            acc.y += a * w1.y + xd * w2.y;
            acc.z += a * w1.z + xd * w2.z;
            acc.w += a * w1.w + xd * w2.w;
        }
        acc.x = fmaxf(acc.x, 0.f); acc.y = fmaxf(acc.y, 0.f);
        acc.z = fmaxf(acc.z, 0.f); acc.w = fmaxf(acc.w, 0.f);
        ((float4*)x1w)[lane] = acc;
        *((float4*)(g_x1 + (size_t)n * 128) + lane) = acc;
        __syncwarp();
        // s1_raw[j] for j = 2*lane, 2*lane+1
        float2 r = ((float2*)pb1s)[lane];
        #pragma unroll 8
        for (int k = 0; k < 128; k++) {
            float xv = x1w[k];
            float2 p = ((float2*)(pw + k * 64))[lane];
            r.x += xv * p.x;
            r.y += xv * p.y;
        }
        // LayerNorm over 64
        float sum = r.x + r.y, sq = r.x * r.x + r.y * r.y;
        #pragma unroll
        for (int o = 16; o; o >>= 1) {
            sum += __shfl_xor_sync(0xffffffffu, sum, o);
            sq  += __shfl_xor_sync(0xffffffffu, sq, o);
        }
        float mu  = sum * (1.f / 64.f);
        float var = sq * (1.f / 64.f) - mu * mu;
        float inv = rsqrtf(var + 1e-5f);
        float2 gg = ((float2*)g1s)[lane];
        float2 bb = ((float2*)be1s)[lane];
        float v0 = (r.x - mu) * inv * gg.x + bb.x;
        float v1 = (r.y - mu) * inv * gg.y + bb.y;
        // softmax / log_softmax over 64
        float mx = fmaxf(v0, v1);
        #pragma unroll
        for (int o = 16; o; o >>= 1) mx = fmaxf(mx, __shfl_xor_sync(0xffffffffu, mx, o));
        float e0 = __expf(v0 - mx), e1 = __expf(v1 - mx);
        float se = e0 + e1;
        #pragma unroll
        for (int o = 16; o; o >>= 1) se += __shfl_xor_sync(0xffffffffu, se, o);
        float lse = __logf(se);
        float rinv = 1.f / se;
        ((float2*)(out + 4 + (size_t)n * 64))[lane] = make_float2(v0 - mx - lse, v1 - mx - lse);
        ((float2*)(g_s + (size_t)n * 64))[lane]     = make_float2(e0 * rinv, e1 * rinv);
    }
}

// ---------------- K3: fused pooled reductions: s^T @ [x1 | A_s | s], den ----------------
__global__ void k_pool() {
    __shared__ float sv[64];
    __shared__ float vv[256];
    __shared__ float degsh;
    __shared__ float redsh[256];
    float acc[4][16];
    #pragma unroll
    for (int i = 0; i < 4; i++)
        #pragma unroll
        for (int j = 0; j < 16; j++) acc[i][j] = 0.f;
    float denp = 0.f;

    int t = threadIdx.x;
    int rg = t >> 4, cg = t & 15;
    int per = (NN + NB3 - 1) / NB3;
    int n0 = blockIdx.x * per;
    int n1 = min(n0 + per, NN);

    for (int n = n0; n < n1; n++) {
        __syncthreads();
        if (t < 128) vv[t] = g_x1[(size_t)n * 128 + t];
        else if (t < 192) vv[t] = g_As[(size_t)n * 64 + (t - 128)];
        else { float s = g_s[(size_t)n * 64 + (t - 192)]; vv[t] = s; sv[t - 192] = s; }
        if (t == 0) degsh = g_deg[n];
        __syncthreads();
        float4 s4 = *(float4*)(sv + rg * 4);
        float vr[16];
        #pragma unroll
        for (int j = 0; j < 16; j += 4) *(float4*)(vr + j) = *(float4*)(vv + cg * 16 + j);
        #pragma unroll
        for (int j = 0; j < 16; j++) {
            acc[0][j] += s4.x * vr[j];
            acc[1][j] += s4.y * vr[j];
            acc[2][j] += s4.z * vr[j];
            acc[3][j] += s4.w * vr[j];
        }
        if (t >= 192) { float s = vv[t]; denp += degsh * s * s; }
    }
    float* base = g_part + (size_t)blockIdx.x * PART_STRIDE;
    #pragma unroll
    for (int i = 0; i < 4; i++)
        #pragma unroll
        for (int j = 0; j < 16; j++)
            base[(rg * 4 + i) * 256 + cg * 16 + j] = acc[i][j];
    redsh[t] = denp; __syncthreads();
    for (int o = 128; o; o >>= 1) { if (t < o) redsh[t] += redsh[t + o]; __syncthreads(); }
    if (t == 0) base[16384] = redsh[0];
}

// ---------------- K3r: reduce partials across blocks ----------------
__global__ void k_reduce() {
    int i = blockIdx.x * blockDim.x + threadIdx.x;
    if (i >= PART_STRIDE) return;
    float s = 0.f;
    for (int b = 0; b < NB3; b++) s += g_part[(size_t)b * PART_STRIDE + i];
    g_red[i] = s;
}

// ---------------- K4m: mc1, o1, edge pruning -> M, deg2 ----------------
__global__ void k_small1(float* __restrict__ out) {
    __shared__ float red[256];
    __shared__ float dsi[64];
    int t = threadIdx.x;
    // ||sTs||_F
    float p = 0.f;
    for (int i = t; i < 4096; i += 256) {
        float v = g_red[(i >> 6) * 256 + 192 + (i & 63)];
        p += v * v;
    }
    red[t] = p; __syncthreads();
    for (int o = 128; o; o >>= 1) { if (t < o) red[t] += red[t + o]; __syncthreads(); }
    float nrm = sqrtf(red[0]); __syncthreads();
    // o1
    float q = 0.f;
    for (int i = t; i < 4096; i += 256) {
        int c = i >> 6, j = i & 63;
        float v = g_red[c * 256 + 192 + j] / (nrm + 1e-10f) - ((c == j) ? 0.125f : 0.f);
        q += v * v;
    }
    red[t] = q; __syncthreads();
    for (int o = 128; o; o >>= 1) { if (t < o) red[t] += red[t + o]; __syncthreads(); }
    float o1 = sqrtf(red[0]); __syncthreads();
    // trace(pooled_adj)
    float tp = (t < 64) ? g_red[t * 256 + 128 + t] : 0.f;
    red[t] = tp; __syncthreads();
    for (int o = 128; o; o >>= 1) { if (t < o) red[t] += red[t + o]; __syncthreads(); }
    if (t == 0) {
        float den = g_red[16384];
        out[0] = -red[0] / (den + 1e-10f);
        out[1] = o1;
    }
    __syncthreads();
    // degree-normalize pruned adjacency
    if (t < 64) {
        float rs = 0.f;
        for (int j = 0; j < 64; j++) if (j != t) rs += g_red[t * 256 + 128 + j];
        dsi[t] = 1.f / (sqrtf(rs) + 1e-15f);
    }
    __syncthreads();
    for (int i = t; i < 4096; i += 256) {
        int c = i >> 6, j = i & 63;
        float a = (c == j) ? 0.f : (g_red[c * 256 + 128 + j] * dsi[c] * dsi[j]);
        g_M[i] = (a > (1.0f / 63.0f)) ? 1.f : 0.f;
    }
    __syncthreads();
    if (t < 64) {
        float d = 0.f;
        for (int j = 0; j < 64; j++) d += g_M[t * 64 + j];
        g_deg2[t] = d;
    }
}

// ---------------- K4a: pooled GraphConv + LN + softmax/log_softmax (per cluster row) ----------------
__global__ void k_layer2(const float* __restrict__ W2rel, const float* __restrict__ b2,
                         const float* __restrict__ W2root,
                         const float* __restrict__ pW2, const float* __restrict__ pb2,
                         const float* __restrict__ g2, const float* __restrict__ be2,
                         float* __restrict__ out) {
    int c = blockIdx.x;     // 0..63
    int t = threadIdx.x;    // 0..127
    __shared__ float Mcol[64], ag[128], pr[128], x2r[128], praw[128], r16[16], v16[16];
    if (t < 64) Mcol[t] = g_M[t * 64 + c];          // M[c'][c]
    pr[t] = g_red[c * 256 + t];                      // pooled_x[c][t]
    __syncthreads();
    float a = 0.f;
    #pragma unroll 16
    for (int cp = 0; cp < 64; cp++) a += Mcol[cp] * g_red[cp * 256 + t];
    ag[t] = a;
    __syncthreads();
    float acc = __ldg(b2 + t);
    #pragma unroll 8
    for (int k = 0; k < 128; k++)
        acc += ag[k] * __ldg(W2rel + t * 128 + k) + pr[k] * __ldg(W2root + t * 128 + k);
    acc = fmaxf(acc, 0.f);
    x2r[t] = acc;
    __syncthreads();
    {
        int j2 = t >> 3, seg = t & 7;
        float p = 0.f;
        for (int k = seg; k < 128; k += 8) p += x2r[k] * __ldg(pW2 + j2 * 128 + k);
        praw[t] = p;
    }
    __syncthreads();
    if (t < 16) {
        float raw = pb2[t];
        for (int s = 0; s < 8; s++) raw += praw[t * 8 + s];
        r16[t] = raw;
    }
    __syncthreads();
    if (t < 16) {
        float mu = 0.f, sq = 0.f;
        for (int j = 0; j < 16; j++) { mu += r16[j]; sq += r16[j] * r16[j]; }
        mu *= (1.f / 16.f);
        float var = sq * (1.f / 16.f) - mu * mu;
        v16[t] = (r16[t] - mu) * rsqrtf(var + 1e-5f) * g2[t] + be2[t];
    }
    __syncthreads();
    if (t < 16) {
        float mx = -1e30f;
        for (int j = 0; j < 16; j++) mx = fmaxf(mx, v16[j]);
        float se = 0.f;
        for (int j = 0; j < 16; j++) se += __expf(v16[j] - mx);
        float e = __expf(v16[t] - mx);
        out[4 + NN * 64 + c * 16 + t] = v16[t] - mx - __logf(se);
        g_s2[c * 16 + t] = e / se;
    }
}

// ---------------- K4b: dense mincut on pooled graph -> mc2, o2 ----------------
__global__ void k_small2(float* __restrict__ out) {
    __shared__ float s2s[NC1 * NC2];
    __shared__ float As2[NC1 * NC2];
    __shared__ float padj[NC2 * NC2];
    __shared__ float sTs[NC2 * NC2];
    __shared__ float red[256];
    int t = threadIdx.x;   // 256
    for (int i = t; i < 1024; i += 256) s2s[i] = g_s2[i];
    __syncthreads();
    for (int i = t; i < 1024; i += 256) {
        int c = i >> 4, j = i & 15;
        float a = 0.f;
        for (int cp = 0; cp < 64; cp++) a += g_M[c * 64 + cp] * s2s[cp * 16 + j];
        As2[i] = a;
    }
    __syncthreads();
    {
        int aI = t >> 4, bI = t & 15;
        float pa = 0.f, st = 0.f;
        for (int c = 0; c < 64; c++) {
            float sa = s2s[c * 16 + aI];
            pa += sa * As2[c * 16 + bI];
            st += sa * s2s[c * 16 + bI];
        }
        padj[t] = pa; sTs[t] = st;
    }
    __syncthreads();
    float dp = 0.f;
    if (t < 64) {
        float accv = 0.f;
        for (int j = 0; j < 16; j++) { float s = s2s[t * 16 + j]; accv += s * s; }
        dp = g_deg2[t] * accv;
    }
    red[t] = dp; __syncthreads();
    for (int o = 128; o; o >>= 1) { if (t < o) red[t] += red[t + o]; __syncthreads(); }
    float den2 = red[0]; __syncthreads();
    float trp = (t < 16) ? padj[t * 16 + t] : 0.f;
    red[t] = trp; __syncthreads();
    for (int o = 128; o; o >>= 1) { if (t < o) red[t] += red[t + o]; __syncthreads(); }
    float tr2 = red[0]; __syncthreads();
    float np = sTs[t] * sTs[t];
    red[t] = np; __syncthreads();
    for (int o = 128; o; o >>= 1) { if (t < o) red[t] += red[t + o]; __syncthreads(); }
    float norm2 = sqrtf(red[0]); __syncthreads();
    float diff = sTs[t] / (norm2 + 1e-10f) - (((t >> 4) == (t & 15)) ? 0.25f : 0.f);
    red[t] = diff * diff; __syncthreads();
    for (int o = 128; o; o >>= 1) { if (t < o) red[t] += red[t + o]; __syncthreads(); }
    if (t == 0) {
        out[2] = -tr2 / (den2 + 1e-10f);
        out[3] = sqrtf(red[0]);
    }
}

// ---------------- launch ----------------
extern "C" void kernel_launch(void* const* d_in, const int* in_sizes, int n_in,
                              void* d_out, int out_size) {
    const float* x     = (const float*)d_in[0];
    const int*   ei    = (const int*)d_in[1];
    const float* mask  = (const float*)d_in[2];
    const float* W1rel = (const float*)d_in[3];
    const float* b1    = (const float*)d_in[4];
    const float* W1rt  = (const float*)d_in[5];
    const float* pW1   = (const float*)d_in[6];
    const float* pb1   = (const float*)d_in[7];
    const float* g1    = (const float*)d_in[8];
    const float* be1   = (const float*)d_in[9];
    const float* W2rel = (const float*)d_in[10];
    const float* b2    = (const float*)d_in[11];
    const float* W2rt  = (const float*)d_in[12];
    const float* pW2   = (const float*)d_in[13];
    const float* pb2   = (const float*)d_in[14];
    const float* g2    = (const float*)d_in[15];
    const float* be2   = (const float*)d_in[16];
    float* out = (float*)d_out;
    const int* row = ei;
    const int* col = ei + EE;

    cudaFuncSetAttribute(k_node, cudaFuncAttributeMaxDynamicSharedMemorySize,
                         K2_SMEM_FLOATS * (int)sizeof(float));

    k_zero<<<(NN * INC / 4 + 255) / 256, 256>>>();
    k_scatter_agg<<<(EE * 16) / 256, 256>>>(x, row, col, mask);
    k_node<<<148, K2_THREADS, K2_SMEM_FLOATS * sizeof(float)>>>(
        x, mask, W1rel, b1, W1rt, pW1, pb1, g1, be1, out);
    k_scatter_As<<<(EE * 16) / 256, 256>>>(row, col);
    k_pool<<<NB3, 256>>>();
    k_reduce<<<(PART_STRIDE + 255) / 256, 256>>>();
    k_small1<<<1, 256>>>(out);
    k_layer2<<<64, 128>>>(W2rel, b2, W2rt, pW2, pb2, g2, be2, out);
    k_small2<<<1, 256>>>(out);
}

// round 4
// speedup vs baseline: 1.4489x; 1.4489x over previous
#include <cuda_runtime.h>

#define NN 50000
#define EE 800000
#define INC 64
#define HID 128
#define NC1 64
#define NC2 16

#define NB3 148
#define PART_SIZE 16385     // 64*256 pooled + 1 den (logical)
#define PART_STRIDE 16400   // padded to 16B multiple for vector stores

typedef unsigned long long u64;

// ---------------- scratch (device globals; no allocation allowed) ----------------
__device__ __align__(256) float g_agg[NN * INC];
__device__ __align__(256) float g_x1[NN * HID];
__device__ __align__(256) float g_s[NN * NC1];
__device__ __align__(256) float g_As[NN * NC1];
__device__ __align__(256) float g_deg[NN];
__device__ __align__(256) float g_part[NB3 * PART_STRIDE];
__device__ __align__(256) float g_red[PART_STRIDE];
__device__ __align__(256) float g_M[NC1 * NC1];
__device__ __align__(256) float g_deg2[NC1];
__device__ __align__(256) float g_s2[NC1 * NC2];

// ---------------- helpers ----------------
__device__ __forceinline__ void red_add_v4(float* p, float4 v) {
    asm volatile("red.global.add.v4.f32 [%0], {%1,%2,%3,%4};"
                 :: "l"(p), "f"(v.x), "f"(v.y), "f"(v.z), "f"(v.w) : "memory");
}
__device__ __forceinline__ void red_add_f32(float* p, float v) {
    asm volatile("red.global.add.f32 [%0], %1;" :: "l"(p), "f"(v) : "memory");
}
__device__ __forceinline__ u64 pack2(float x, float y) {
    u64 r; asm("mov.b64 %0, {%1, %2};" : "=l"(r) : "f"(x), "f"(y)); return r;
}
__device__ __forceinline__ void unpack2(float& x, float& y, u64 r) {
    asm("mov.b64 {%0, %1}, %2;" : "=f"(x), "=f"(y) : "l"(r));
}
__device__ __forceinline__ void fma2(u64& d, u64 a, u64 b) {
    asm("fma.rn.f32x2 %0, %1, %2, %0;" : "+l"(d) : "l"(a), "l"(b));
}

// ---------------- K0: zero accumulators ----------------
__global__ void k_zero() {
    int i = blockIdx.x * blockDim.x + threadIdx.x;
    float4 z = make_float4(0.f, 0.f, 0.f, 0.f);
    if (i < NN * INC / 4) ((float4*)g_agg)[i] = z;
    if (i < NN * NC1 / 4) ((float4*)g_As)[i] = z;
    if (i < NN / 4)       ((float4*)g_deg)[i] = z;
}

// ---------------- K1: agg[col[e]] += drop_mask[row[e]] * x[row[e]] ----------------
__global__ void k_scatter_agg(const float* __restrict__ x,
                              const int* __restrict__ row,
                              const int* __restrict__ col,
                              const float* __restrict__ mask) {
    int t = blockIdx.x * blockDim.x + threadIdx.x;   // E*16 threads
    int e = t >> 4, c4 = t & 15;
    int r = __ldg(row + e);
    int c = __ldg(col + e);
    float m = __ldg(mask + r);
    float4 v = __ldg((const float4*)(x + (size_t)r * INC) + c4);
    v.x *= m; v.y *= m; v.z *= m; v.w *= m;
    red_add_v4(g_agg + (size_t)c * INC + c4 * 4, v);
}

// ---------------- K2b: A_s[row[e]] += s[col[e]]; deg[row[e]] += 1 ----------------
__global__ void k_scatter_As(const int* __restrict__ row,
                             const int* __restrict__ col) {
    int t = blockIdx.x * blockDim.x + threadIdx.x;   // E*16 threads
    int e = t >> 4, c4 = t & 15;
    int r = __ldg(row + e);
    int c = __ldg(col + e);
    float4 v = __ldg((const float4*)(g_s + (size_t)c * NC1) + c4);
    red_add_v4(g_As + (size_t)r * NC1 + c4 * 4, v);
    if (c4 == 0) red_add_f32(g_deg + r, 1.0f);
}

// ---------------- K2: per-node fused GraphConv+ReLU, pool-proj, LN, softmax/log_softmax
//   4 nodes per warp per iteration (amortize weight LDS), packed f32x2 FMA.
#define K2_THREADS 512
// smem floats: wrel_t 8192 | wroot_t 8192 | pw_t 8192 | b1 128 | pb1/g1/be1 3*64 | ins 16*512 | x1 16*512
#define K2_SMEM_FLOATS (8192*3 + 128 + 192 + 8192 + 8192)

__global__ void k_node(const float* __restrict__ x, const float* __restrict__ mask,
                       const float* __restrict__ W1rel, const float* __restrict__ b1,
                       const float* __restrict__ W1root,
                       const float* __restrict__ pW1, const float* __restrict__ pb1,
                       const float* __restrict__ g1, const float* __restrict__ be1,
                       float* __restrict__ out) {
    extern __shared__ float sm[];
    float* wrel  = sm;
    float* wroot = wrel + 8192;
    float* pwS   = wroot + 8192;
    float* b1s   = pwS + 8192;
    float* pb1s  = b1s + 128;
    float* g1s   = pb1s + 64;
    float* be1s  = g1s + 64;
    float* ins   = be1s + 64;      // [16 warps][4 nodes][128] : agg | xdrop
    float* x1sh  = ins + 8192;     // [16 warps][4 nodes][128]

    int tid = threadIdx.x;
    for (int i = tid; i < 8192; i += K2_THREADS) {
        int j = i >> 6, k = i & 63;                 // W1* are [128][64]
        wrel[k * 128 + j]  = W1rel[i];
        wroot[k * 128 + j] = W1root[i];
    }
    for (int i = tid; i < 8192; i += K2_THREADS) {
        int j = i >> 7, k = i & 127;                // pW1 is [64][128]
        pwS[k * 64 + j] = pW1[i];
    }
    if (tid < 128) b1s[tid] = b1[tid];
    if (tid < 64) { pb1s[tid] = pb1[tid]; g1s[tid] = g1[tid]; be1s[tid] = be1[tid]; }
    __syncthreads();

    int w = tid >> 5, lane = tid & 31;
    int per = (NN + gridDim.x - 1) / gridDim.x;
    int n0 = blockIdx.x * per;
    int n1 = min(n0 + per, NN);
    float* insw = ins + w * 512;
    float* x1w  = x1sh + w * 512;

    // bias packs (loop-invariant)
    float4 bv = ((float4*)b1s)[lane];
    u64 b_lo = pack2(bv.x, bv.y), b_hi = pack2(bv.z, bv.w);
    float2 pbv = ((float2*)pb1s)[lane];
    u64 pb_pk = pack2(pbv.x, pbv.y);
    float2 gg = ((float2*)g1s)[lane];
    float2 bb = ((float2*)be1s)[lane];

    for (int base = n0; base < n1; base += 64) {
        int nb = base + w * 4;
        // ---- stage 4 nodes: agg (64) | xdrop (64) each ----
        #pragma unroll
        for (int q = 0; q < 4; q++) {
            int node = nb + q;
            int cn = node < NN ? node : NN - 1;
            if (lane < 16) {
                ((float4*)(insw + q * 128))[lane] =
                    *((const float4*)(g_agg + (size_t)cn * 64) + lane);
            } else {
                int k4 = lane - 16;
                float m = __ldg(mask + cn);
                float4 v = __ldg((const float4*)(x + (size_t)cn * 64) + k4);
                v.x *= m; v.y *= m; v.z *= m; v.w *= m;
                ((float4*)(insw + q * 128))[16 + k4] = v;
            }
        }
        __syncwarp();

        // ---- GEMM1: x1[j] for j=4*lane..+3, 4 nodes, packed f32x2 ----
        u64 acc_lo[4], acc_hi[4];
        #pragma unroll
        for (int q = 0; q < 4; q++) { acc_lo[q] = b_lo; acc_hi[q] = b_hi; }
        #pragma unroll
        for (int k4 = 0; k4 < 16; k4++) {
            float4 av[4], xv[4];
            #pragma unroll
            for (int q = 0; q < 4; q++) {
                av[q] = ((float4*)(insw + q * 128))[k4];
                xv[q] = ((float4*)(insw + q * 128 + 64))[k4];
            }
            #pragma unroll
            for (int kk = 0; kk < 4; kk++) {
                int k = k4 * 4 + kk;
                ulonglong2 w1 = ((ulonglong2*)(wrel + k * 128))[lane];
                ulonglong2 w2 = ((ulonglong2*)(wroot + k * 128))[lane];
                #pragma unroll
                for (int q = 0; q < 4; q++) {
                    float a  = ((const float*)&av[q])[kk];
                    float xd = ((const float*)&xv[q])[kk];
                    u64 ap = pack2(a, a);
                    u64 xp = pack2(xd, xd);
                    fma2(acc_lo[q], ap, w1.x);
                    fma2(acc_hi[q], ap, w1.y);
                    fma2(acc_lo[q], xp, w2.x);
                    fma2(acc_hi[q], xp, w2.y);
                }
            }
        }
        #pragma unroll
        for (int q = 0; q < 4; q++) {
            float f0, f1, f2, f3;
            unpack2(f0, f1, acc_lo[q]);
            unpack2(f2, f3, acc_hi[q]);
            f0 = fmaxf(f0, 0.f); f1 = fmaxf(f1, 0.f);
            f2 = fmaxf(f2, 0.f); f3 = fmaxf(f3, 0.f);
            float4 r4 = make_float4(f0, f1, f2, f3);
            ((float4*)(x1w + q * 128))[lane] = r4;
            int node = nb + q;
            if (node < n1) *((float4*)(g_x1 + (size_t)node * 128) + lane) = r4;
        }
        __syncwarp();

        // ---- proj: s1_raw[j] for j=2*lane,2*lane+1, 4 nodes ----
        u64 pacc[4];
        #pragma unroll
        for (int q = 0; q < 4; q++) pacc[q] = pb_pk;
        #pragma unroll
        for (int k4 = 0; k4 < 32; k4++) {
            float4 xv[4];
            #pragma unroll
            for (int q = 0; q < 4; q++) xv[q] = ((float4*)(x1w + q * 128))[k4];
            #pragma unroll
            for (int kk = 0; kk < 4; kk++) {
                int k = k4 * 4 + kk;
                u64 pw2 = ((const u64*)(pwS + k * 64))[lane];
                #pragma unroll
                for (int q = 0; q < 4; q++) {
                    float xvk = ((const float*)&xv[q])[kk];
                    fma2(pacc[q], pack2(xvk, xvk), pw2);
                }
            }
        }

        // ---- LN + softmax/log_softmax per node ----
        #pragma unroll
        for (int q = 0; q < 4; q++) {
            int node = nb + q;
            float rx, ry;
            unpack2(rx, ry, pacc[q]);
            float sum = rx + ry, sq = rx * rx + ry * ry;
            #pragma unroll
            for (int o = 16; o; o >>= 1) {
                sum += __shfl_xor_sync(0xffffffffu, sum, o);
                sq  += __shfl_xor_sync(0xffffffffu, sq, o);
            }
            float mu  = sum * (1.f / 64.f);
            float var = sq * (1.f / 64.f) - mu * mu;
            float inv = rsqrtf(var + 1e-5f);
            float v0 = (rx - mu) * inv * gg.x + bb.x;
            float v1 = (ry - mu) * inv * gg.y + bb.y;
            float mx = fmaxf(v0, v1);
            #pragma unroll
            for (int o = 16; o; o >>= 1) mx = fmaxf(mx, __shfl_xor_sync(0xffffffffu, mx, o));
            float e0 = __expf(v0 - mx), e1 = __expf(v1 - mx);
            float se = e0 + e1;
            #pragma unroll
            for (int o = 16; o; o >>= 1) se += __shfl_xor_sync(0xffffffffu, se, o);
            float lse = __logf(se);
            float rinv = 1.f / se;
            if (node < n1) {
                ((float2*)(out + 4 + (size_t)node * 64))[lane] = make_float2(v0 - mx - lse, v1 - mx - lse);
                ((float2*)(g_s + (size_t)node * 64))[lane]     = make_float2(e0 * rinv, e1 * rinv);
            }
        }
        __syncwarp();
    }
}

// ---------------- K3: fused pooled reductions: s^T @ [x1 | A_s | s], den ----------------
// double-buffered smem, register prefetch, one barrier per node, packed f32x2
__global__ void k_pool() {
    __shared__ __align__(16) float vv[2][256];
    __shared__ float redsh[256];

    int t = threadIdx.x;
    int rg = t >> 4, cg = t & 15;
    int per = (NN + NB3 - 1) / NB3;
    int n0 = blockIdx.x * per;
    int n1 = min(n0 + per, NN);

    const float* src;
    int stride;
    if (t < 128)      { src = g_x1 + t;        stride = 128; }
    else if (t < 192) { src = g_As + (t - 128); stride = 64; }
    else              { src = g_s  + (t - 192); stride = 64; }

    u64 acc[4][8];
    #pragma unroll
    for (int i = 0; i < 4; i++)
        #pragma unroll
        for (int j = 0; j < 8; j++) acc[i][j] = 0ULL;
    float denp = 0.f;

    float cur  = src[(size_t)n0 * stride];
    float dcur = (t >= 192) ? __ldg(g_deg + n0) : 0.f;

    for (int n = n0; n < n1; n++) {
        int p = (n - n0) & 1;
        vv[p][t] = cur;
        // prefetch next node
        float nxt = 0.f, dnxt = 0.f;
        if (n + 1 < n1) {
            nxt = src[(size_t)(n + 1) * stride];
            if (t >= 192) dnxt = __ldg(g_deg + (n + 1));
        }
        if (t >= 192) denp += dcur * cur * cur;
        __syncthreads();

        float4 s4 = *(const float4*)&vv[p][192 + rg * 4];
        u64 s0 = pack2(s4.x, s4.x), s1 = pack2(s4.y, s4.y);
        u64 s2 = pack2(s4.z, s4.z), s3 = pack2(s4.w, s4.w);
        const ulonglong2* vp = (const ulonglong2*)&vv[p][cg * 16];
        #pragma unroll
        for (int h = 0; h < 4; h++) {
            ulonglong2 b2v = vp[h];
            fma2(acc[0][2*h], s0, b2v.x); fma2(acc[0][2*h+1], s0, b2v.y);
            fma2(acc[1][2*h], s1, b2v.x); fma2(acc[1][2*h+1], s1, b2v.y);
            fma2(acc[2][2*h], s2, b2v.x); fma2(acc[2][2*h+1], s2, b2v.y);
            fma2(acc[3][2*h], s3, b2v.x); fma2(acc[3][2*h+1], s3, b2v.y);
        }
        cur = nxt; dcur = dnxt;
    }

    float* base = g_part + (size_t)blockIdx.x * PART_STRIDE;  // 16B-aligned (PART_STRIDE % 4 == 0)
    #pragma unroll
    for (int i = 0; i < 4; i++)
        #pragma unroll
        for (int j = 0; j < 8; j++) {
            float f0, f1;
            unpack2(f0, f1, acc[i][j]);
            ((float2*)(base + (rg * 4 + i) * 256 + cg * 16))[j] = make_float2(f0, f1);
        }
    redsh[t] = denp; __syncthreads();
    for (int o = 128; o; o >>= 1) { if (t < o) redsh[t] += redsh[t + o]; __syncthreads(); }
    if (t == 0) base[16384] = redsh[0];
}

// ---------------- K3r: reduce partials across blocks ----------------
__global__ void k_reduce() {
    int i = blockIdx.x * blockDim.x + threadIdx.x;
    if (i >= PART_SIZE) return;
    float s = 0.f;
    for (int b = 0; b < NB3; b++) s += g_part[(size_t)b * PART_STRIDE + i];
    g_red[i] = s;
}

// ---------------- K4m: mc1, o1, edge pruning -> M, deg2 ----------------
__global__ void k_small1(float* __restrict__ out) {
    __shared__ float red[256];
    __shared__ float dsi[64];
    int t = threadIdx.x;
    float p = 0.f;
    for (int i = t; i < 4096; i += 256) {
        float v = g_red[(i >> 6) * 256 + 192 + (i & 63)];
        p += v * v;
    }
    red[t] = p; __syncthreads();
    for (int o = 128; o; o >>= 1) { if (t < o) red[t] += red[t + o]; __syncthreads(); }
    float nrm = sqrtf(red[0]); __syncthreads();
    float q = 0.f;
    for (int i = t; i < 4096; i += 256) {
        int c = i >> 6, j = i & 63;
        float v = g_red[c * 256 + 192 + j] / (nrm + 1e-10f) - ((c == j) ? 0.125f : 0.f);
        q += v * v;
    }
    red[t] = q; __syncthreads();
    for (int o = 128; o; o >>= 1) { if (t < o) red[t] += red[t + o]; __syncthreads(); }
    float o1 = sqrtf(red[0]); __syncthreads();
    float tp = (t < 64) ? g_red[t * 256 + 128 + t] : 0.f;
    red[t] = tp; __syncthreads();
    for (int o = 128; o; o >>= 1) { if (t < o) red[t] += red[t + o]; __syncthreads(); }
    if (t == 0) {
        float den = g_red[16384];
        out[0] = -red[0] / (den + 1e-10f);
        out[1] = o1;
    }
    __syncthreads();
    if (t < 64) {
        float rs = 0.f;
        for (int j = 0; j < 64; j++) if (j != t) rs += g_red[t * 256 + 128 + j];
        dsi[t] = 1.f / (sqrtf(rs) + 1e-15f);
    }
    __syncthreads();
    for (int i = t; i < 4096; i += 256) {
        int c = i >> 6, j = i & 63;
        float a = (c == j) ? 0.f : (g_red[c * 256 + 128 + j] * dsi[c] * dsi[j]);
        g_M[i] = (a > (1.0f / 63.0f)) ? 1.f : 0.f;
    }
    __syncthreads();
    if (t < 64) {
        float d = 0.f;
        for (int j = 0; j < 64; j++) d += g_M[t * 64 + j];
        g_deg2[t] = d;
    }
}

// ---------------- K4a: pooled GraphConv + LN + softmax/log_softmax ----------------
__global__ void k_layer2(const float* __restrict__ W2rel, const float* __restrict__ b2,
                         const float* __restrict__ W2root,
                         const float* __restrict__ pW2, const float* __restrict__ pb2,
                         const float* __restrict__ g2, const float* __restrict__ be2,
                         float* __restrict__ out) {
    int c = blockIdx.x;     // 0..63
    int t = threadIdx.x;    // 0..127
    __shared__ float Mcol[64], ag[128], pr[128], x2r[128], praw[128], r16[16], v16[16];
    if (t < 64) Mcol[t] = g_M[t * 64 + c];
    pr[t] = g_red[c * 256 + t];
    __syncthreads();
    float a = 0.f;
    #pragma unroll 16
    for (int cp = 0; cp < 64; cp++) a += Mcol[cp] * g_red[cp * 256 + t];
    ag[t] = a;
    __syncthreads();
    float acc = __ldg(b2 + t);
    #pragma unroll 8
    for (int k = 0; k < 128; k++)
        acc += ag[k] * __ldg(W2rel + t * 128 + k) + pr[k] * __ldg(W2root + t * 128 + k);
    acc = fmaxf(acc, 0.f);
    x2r[t] = acc;
    __syncthreads();
    {
        int j2 = t >> 3, seg = t & 7;
        float p = 0.f;
        for (int k = seg; k < 128; k += 8) p += x2r[k] * __ldg(pW2 + j2 * 128 + k);
        praw[t] = p;
    }
    __syncthreads();
    if (t < 16) {
        float raw = pb2[t];
        for (int s = 0; s < 8; s++) raw += praw[t * 8 + s];
        r16[t] = raw;
    }
    __syncthreads();
    if (t < 16) {
        float mu = 0.f, sq = 0.f;
        for (int j = 0; j < 16; j++) { mu += r16[j]; sq += r16[j] * r16[j]; }
        mu *= (1.f / 16.f);
        float var = sq * (1.f / 16.f) - mu * mu;
        v16[t] = (r16[t] - mu) * rsqrtf(var + 1e-5f) * g2[t] + be2[t];
    }
    __syncthreads();
    if (t < 16) {
        float mx = -1e30f;
        for (int j = 0; j < 16; j++) mx = fmaxf(mx, v16[j]);
        float se = 0.f;
        for (int j = 0; j < 16; j++) se += __expf(v16[j] - mx);
        float e = __expf(v16[t] - mx);
        out[4 + NN * 64 + c * 16 + t] = v16[t] - mx - __logf(se);
        g_s2[c * 16 + t] = e / se;
    }
}

// ---------------- K4b: dense mincut on pooled graph -> mc2, o2 ----------------
__global__ void k_small2(float* __restrict__ out) {
    __shared__ float s2s[NC1 * NC2];
    __shared__ float As2[NC1 * NC2];
    __shared__ float padj[NC2 * NC2];
    __shared__ float sTs[NC2 * NC2];
    __shared__ float red[256];
    int t = threadIdx.x;   // 256
    for (int i = t; i < 1024; i += 256) s2s[i] = g_s2[i];
    __syncthreads();
    for (int i = t; i < 1024; i += 256) {
        int c = i >> 4, j = i & 15;
        float a = 0.f;
        for (int cp = 0; cp < 64; cp++) a += g_M[c * 64 + cp] * s2s[cp * 16 + j];
        As2[i] = a;
    }
    __syncthreads();
    {
        int aI = t >> 4, bI = t & 15;
        float pa = 0.f, st = 0.f;
        for (int c = 0; c < 64; c++) {
            float sa = s2s[c * 16 + aI];
            pa += sa * As2[c * 16 + bI];
            st += sa * s2s[c * 16 + bI];
        }
        padj[t] = pa; sTs[t] = st;
    }
    __syncthreads();
    float dp = 0.f;
    if (t < 64) {
        float accv = 0.f;
        for (int j = 0; j < 16; j++) { float s = s2s[t * 16 + j]; accv += s * s; }
        dp = g_deg2[t] * accv;
    }
    red[t] = dp; __syncthreads();
    for (int o = 128; o; o >>= 1) { if (t < o) red[t] += red[t + o]; __syncthreads(); }
    float den2 = red[0]; __syncthreads();
    float trp = (t < 16) ? padj[t * 16 + t] : 0.f;
    red[t] = trp; __syncthreads();
    for (int o = 128; o; o >>= 1) { if (t < o) red[t] += red[t + o]; __syncthreads(); }
    float tr2 = red[0]; __syncthreads();
    float np = sTs[t] * sTs[t];
    red[t] = np; __syncthreads();
    for (int o = 128; o; o >>= 1) { if (t < o) red[t] += red[t + o]; __syncthreads(); }
    float norm2 = sqrtf(red[0]); __syncthreads();
    float diff = sTs[t] / (norm2 + 1e-10f) - (((t >> 4) == (t & 15)) ? 0.25f : 0.f);
    red[t] = diff * diff; __syncthreads();
    for (int o = 128; o; o >>= 1) { if (t < o) red[t] += red[t + o]; __syncthreads(); }
    if (t == 0) {
        out[2] = -tr2 / (den2 + 1e-10f);
        out[3] = sqrtf(red[0]);
    }
}

// ---------------- launch ----------------
extern "C" void kernel_launch(void* const* d_in, const int* in_sizes, int n_in,
                              void* d_out, int out_size) {
    const float* x     = (const float*)d_in[0];
    const int*   ei    = (const int*)d_in[1];
    const float* mask  = (const float*)d_in[2];
    const float* W1rel = (const float*)d_in[3];
    const float* b1    = (const float*)d_in[4];
    const float* W1rt  = (const float*)d_in[5];
    const float* pW1   = (const float*)d_in[6];
    const float* pb1   = (const float*)d_in[7];
    const float* g1    = (const float*)d_in[8];
    const float* be1   = (const float*)d_in[9];
    const float* W2rel = (const float*)d_in[10];
    const float* b2    = (const float*)d_in[11];
    const float* W2rt  = (const float*)d_in[12];
    const float* pW2   = (const float*)d_in[13];
    const float* pb2   = (const float*)d_in[14];
    const float* g2    = (const float*)d_in[15];
    const float* be2   = (const float*)d_in[16];
    float* out = (float*)d_out;
    const int* row = ei;
    const int* col = ei + EE;

    cudaFuncSetAttribute(k_node, cudaFuncAttributeMaxDynamicSharedMemorySize,
                         K2_SMEM_FLOATS * (int)sizeof(float));

    k_zero<<<(NN * INC / 4 + 255) / 256, 256>>>();
    k_scatter_agg<<<(EE * 16) / 256, 256>>>(x, row, col, mask);
    k_node<<<148, K2_THREADS, K2_SMEM_FLOATS * sizeof(float)>>>(
        x, mask, W1rel, b1, W1rt, pW1, pb1, g1, be1, out);
    k_scatter_As<<<(EE * 16) / 256, 256>>>(row, col);
    k_pool<<<NB3, 256>>>();
    k_reduce<<<(PART_SIZE + 255) / 256, 256>>>();
    k_small1<<<1, 256>>>(out);
    k_layer2<<<64, 128>>>(W2rel, b2, W2rt, pW2, pb2, g2, be2, out);
    k_small2<<<1, 256>>>(out);
}

// round 5
// speedup vs baseline: 1.7416x; 1.2020x over previous
#include <cuda_runtime.h>

#define NN 50000
#define EE 800000
#define INC 64
#define HID 128
#define NC1 64
#define NC2 16

#define NB3 148
#define PART_SIZE 16385     // 64*256 pooled + 1 den (logical)
#define PART_STRIDE 16400   // padded to 16B multiple for vector stores

typedef unsigned long long u64;

// ---------------- scratch (device globals; no allocation allowed) ----------------
__device__ __align__(256) float g_agg[NN * INC];
__device__ __align__(256) float g_x1[NN * HID];
__device__ __align__(256) float g_s[NN * NC1];
__device__ __align__(256) float g_As[NN * NC1];
__device__ __align__(256) float g_deg[NN];
__device__ __align__(256) float g_part[NB3 * PART_STRIDE];
__device__ __align__(256) float g_red[PART_STRIDE];
__device__ __align__(256) float g_M[NC1 * NC1];
__device__ __align__(256) float g_s2[NC1 * NC2];

// ---------------- helpers ----------------
__device__ __forceinline__ void red_add_v4(float* p, float4 v) {
    asm volatile("red.global.add.v4.f32 [%0], {%1,%2,%3,%4};"
                 :: "l"(p), "f"(v.x), "f"(v.y), "f"(v.z), "f"(v.w) : "memory");
}
__device__ __forceinline__ void red_add_f32(float* p, float v) {
    asm volatile("red.global.add.f32 [%0], %1;" :: "l"(p), "f"(v) : "memory");
}
__device__ __forceinline__ u64 pack2(float x, float y) {
    u64 r; asm("mov.b64 %0, {%1, %2};" : "=l"(r) : "f"(x), "f"(y)); return r;
}
__device__ __forceinline__ void unpack2(float& x, float& y, u64 r) {
    asm("mov.b64 {%0, %1}, %2;" : "=f"(x), "=f"(y) : "l"(r));
}
__device__ __forceinline__ void fma2(u64& d, u64 a, u64 b) {
    asm("fma.rn.f32x2 %0, %1, %2, %0;" : "+l"(d) : "l"(a), "l"(b));
}

// ---------------- K0: zero accumulators ----------------
__global__ void k_zero() {
    int i = blockIdx.x * blockDim.x + threadIdx.x;
    float4 z = make_float4(0.f, 0.f, 0.f, 0.f);
    if (i < NN * INC / 4) ((float4*)g_agg)[i] = z;
    if (i < NN * NC1 / 4) ((float4*)g_As)[i] = z;
    if (i < NN / 4)       ((float4*)g_deg)[i] = z;
}

// ---------------- K1: agg[col[e]] += drop_mask[row[e]] * x[row[e]]; deg[row[e]] += 1
// mask is exactly 0.0 or 1.0 -> skip gather+RED for masked-out source rows (p=0.5)
__global__ void k_scatter_agg(const float* __restrict__ x,
                              const int* __restrict__ row,
                              const int* __restrict__ col,
                              const float* __restrict__ mask) {
    int t = blockIdx.x * blockDim.x + threadIdx.x;   // E*16 threads
    int e = t >> 4, c4 = t & 15;
    int r = __ldg(row + e);
    if (c4 == 0) red_add_f32(g_deg + r, 1.0f);       // degree of source row (all edges)
    float m = __ldg(mask + r);
    if (m != 0.f) {
        int c = __ldg(col + e);
        float4 v = __ldg((const float4*)(x + (size_t)r * INC) + c4);  // m == 1 exactly
        red_add_v4(g_agg + (size_t)c * INC + c4 * 4, v);
    }
}

// ---------------- K2b: A_s[row[e]] += s[col[e]] ----------------
__global__ void k_scatter_As(const int* __restrict__ row,
                             const int* __restrict__ col) {
    int t = blockIdx.x * blockDim.x + threadIdx.x;   // E*16 threads
    int e = t >> 4, c4 = t & 15;
    int r = __ldg(row + e);
    int c = __ldg(col + e);
    float4 v = __ldg((const float4*)(g_s + (size_t)c * NC1) + c4);
    red_add_v4(g_As + (size_t)r * NC1 + c4 * 4, v);
}

// ---------------- K2: per-node fused GraphConv+ReLU, pool-proj, LN, softmax/log_softmax
//   6 nodes per warp per iteration (amortize weight LDS), packed f32x2 FMA.
#define K2_Q 6
#define K2_THREADS 512
// smem floats: wrel_t 8192 | wroot_t 8192 | pw_t 8192 | b1 128 | pb1/g1/be1 3*64 | ins 16*Q*128 | x1 16*Q*128
#define K2_SMEM_FLOATS (8192*3 + 128 + 192 + 16*K2_Q*128*2)

__global__ void k_node(const float* __restrict__ x, const float* __restrict__ mask,
                       const float* __restrict__ W1rel, const float* __restrict__ b1,
                       const float* __restrict__ W1root,
                       const float* __restrict__ pW1, const float* __restrict__ pb1,
                       const float* __restrict__ g1, const float* __restrict__ be1,
                       float* __restrict__ out) {
    extern __shared__ float sm[];
    float* wrel  = sm;
    float* wroot = wrel + 8192;
    float* pwS   = wroot + 8192;
    float* b1s   = pwS + 8192;
    float* pb1s  = b1s + 128;
    float* g1s   = pb1s + 64;
    float* be1s  = g1s + 64;
    float* ins   = be1s + 64;              // [16 warps][Q nodes][128] : agg | xdrop
    float* x1sh  = ins + 16*K2_Q*128;      // [16 warps][Q nodes][128]

    int tid = threadIdx.x;
    for (int i = tid; i < 8192; i += K2_THREADS) {
        int j = i >> 6, k = i & 63;                 // W1* are [128][64]
        wrel[k * 128 + j]  = W1rel[i];
        wroot[k * 128 + j] = W1root[i];
    }
    for (int i = tid; i < 8192; i += K2_THREADS) {
        int j = i >> 7, k = i & 127;                // pW1 is [64][128]
        pwS[k * 64 + j] = pW1[i];
    }
    if (tid < 128) b1s[tid] = b1[tid];
    if (tid < 64) { pb1s[tid] = pb1[tid]; g1s[tid] = g1[tid]; be1s[tid] = be1[tid]; }
    __syncthreads();

    int w = tid >> 5, lane = tid & 31;
    int per = (NN + gridDim.x - 1) / gridDim.x;
    int n0 = blockIdx.x * per;
    int n1 = min(n0 + per, NN);
    float* insw = ins + w * (K2_Q * 128);
    float* x1w  = x1sh + w * (K2_Q * 128);

    // bias packs (loop-invariant)
    float4 bv = ((float4*)b1s)[lane];
    u64 b_lo = pack2(bv.x, bv.y), b_hi = pack2(bv.z, bv.w);
    float2 pbv = ((float2*)pb1s)[lane];
    u64 pb_pk = pack2(pbv.x, pbv.y);
    float2 gg = ((float2*)g1s)[lane];
    float2 bb = ((float2*)be1s)[lane];

    for (int base = n0; base < n1; base += 16 * K2_Q) {
        int nb = base + w * K2_Q;
        // ---- stage Q nodes: agg (64) | xdrop (64) each ----
        #pragma unroll
        for (int q = 0; q < K2_Q; q++) {
            int node = nb + q;
            int cn = node < NN ? node : NN - 1;
            if (lane < 16) {
                ((float4*)(insw + q * 128))[lane] =
                    *((const float4*)(g_agg + (size_t)cn * 64) + lane);
            } else {
                int k4 = lane - 16;
                float m = __ldg(mask + cn);
                float4 v = __ldg((const float4*)(x + (size_t)cn * 64) + k4);
                v.x *= m; v.y *= m; v.z *= m; v.w *= m;
                ((float4*)(insw + q * 128))[16 + k4] = v;
            }
        }
        __syncwarp();

        // ---- GEMM1: x1[j] for j=4*lane..+3, Q nodes, packed f32x2 ----
        u64 acc_lo[K2_Q], acc_hi[K2_Q];
        #pragma unroll
        for (int q = 0; q < K2_Q; q++) { acc_lo[q] = b_lo; acc_hi[q] = b_hi; }
        #pragma unroll
        for (int k4 = 0; k4 < 16; k4++) {
            float4 av[K2_Q], xv[K2_Q];
            #pragma unroll
            for (int q = 0; q < K2_Q; q++) {
                av[q] = ((float4*)(insw + q * 128))[k4];
                xv[q] = ((float4*)(insw + q * 128 + 64))[k4];
            }
            #pragma unroll
            for (int kk = 0; kk < 4; kk++) {
                int k = k4 * 4 + kk;
                ulonglong2 w1 = ((ulonglong2*)(wrel + k * 128))[lane];
                ulonglong2 w2 = ((ulonglong2*)(wroot + k * 128))[lane];
                #pragma unroll
                for (int q = 0; q < K2_Q; q++) {
                    float a  = ((const float*)&av[q])[kk];
                    float xd = ((const float*)&xv[q])[kk];
                    u64 ap = pack2(a, a);
                    u64 xp = pack2(xd, xd);
                    fma2(acc_lo[q], ap, w1.x);
                    fma2(acc_hi[q], ap, w1.y);
                    fma2(acc_lo[q], xp, w2.x);
                    fma2(acc_hi[q], xp, w2.y);
                }
            }
        }
        #pragma unroll
        for (int q = 0; q < K2_Q; q++) {
            float f0, f1, f2, f3;
            unpack2(f0, f1, acc_lo[q]);
            unpack2(f2, f3, acc_hi[q]);
            f0 = fmaxf(f0, 0.f); f1 = fmaxf(f1, 0.f);
            f2 = fmaxf(f2, 0.f); f3 = fmaxf(f3, 0.f);
            float4 r4 = make_float4(f0, f1, f2, f3);
            ((float4*)(x1w + q * 128))[lane] = r4;
            int node = nb + q;
            if (node < n1) *((float4*)(g_x1 + (size_t)node * 128) + lane) = r4;
        }
        __syncwarp();

        // ---- proj: s1_raw[j] for j=2*lane,2*lane+1, Q nodes ----
        u64 pacc[K2_Q];
        #pragma unroll
        for (int q = 0; q < K2_Q; q++) pacc[q] = pb_pk;
        #pragma unroll
        for (int k4 = 0; k4 < 32; k4++) {
            float4 xv[K2_Q];
            #pragma unroll
            for (int q = 0; q < K2_Q; q++) xv[q] = ((float4*)(x1w + q * 128))[k4];
            #pragma unroll
            for (int kk = 0; kk < 4; kk++) {
                int k = k4 * 4 + kk;
                u64 pw2 = ((const u64*)(pwS + k * 64))[lane];
                #pragma unroll
                for (int q = 0; q < K2_Q; q++) {
                    float xvk = ((const float*)&xv[q])[kk];
                    fma2(pacc[q], pack2(xvk, xvk), pw2);
                }
            }
        }

        // ---- LN + softmax/log_softmax per node ----
        #pragma unroll
        for (int q = 0; q < K2_Q; q++) {
            int node = nb + q;
            float rx, ry;
            unpack2(rx, ry, pacc[q]);
            float sum = rx + ry, sq = rx * rx + ry * ry;
            #pragma unroll
            for (int o = 16; o; o >>= 1) {
                sum += __shfl_xor_sync(0xffffffffu, sum, o);
                sq  += __shfl_xor_sync(0xffffffffu, sq, o);
            }
            float mu  = sum * (1.f / 64.f);
            float var = sq * (1.f / 64.f) - mu * mu;
            float inv = rsqrtf(var + 1e-5f);
            float v0 = (rx - mu) * inv * gg.x + bb.x;
            float v1 = (ry - mu) * inv * gg.y + bb.y;
            float mx = fmaxf(v0, v1);
            #pragma unroll
            for (int o = 16; o; o >>= 1) mx = fmaxf(mx, __shfl_xor_sync(0xffffffffu, mx, o));
            float e0 = __expf(v0 - mx), e1 = __expf(v1 - mx);
            float se = e0 + e1;
            #pragma unroll
            for (int o = 16; o; o >>= 1) se += __shfl_xor_sync(0xffffffffu, se, o);
            float lse = __logf(se);
            float rinv = 1.f / se;
            if (node < n1) {
                ((float2*)(out + 4 + (size_t)node * 64))[lane] = make_float2(v0 - mx - lse, v1 - mx - lse);
                ((float2*)(g_s + (size_t)node * 64))[lane]     = make_float2(e0 * rinv, e1 * rinv);
            }
        }
        __syncwarp();
    }
}

// ---------------- K3: fused pooled reductions: s^T @ [x1 | A_s | s], den ----------------
// 4 nodes per barrier, double-buffered smem, register prefetch, packed f32x2
__global__ void k_pool() {
    __shared__ __align__(16) float vv[2][4][256];
    __shared__ float redsh[256];

    int t = threadIdx.x;
    int rg = t >> 4, cg = t & 15;
    int per = (NN + NB3 - 1) / NB3;
    int n0 = blockIdx.x * per;
    int n1 = min(n0 + per, NN);

    const float* src;
    int stride;
    if (t < 128)      { src = g_x1 + t;        stride = 128; }
    else if (t < 192) { src = g_As + (t - 128); stride = 64; }
    else              { src = g_s  + (t - 192); stride = 64; }

    u64 acc[4][8];
    #pragma unroll
    for (int i = 0; i < 4; i++)
        #pragma unroll
        for (int j = 0; j < 8; j++) acc[i][j] = 0ULL;
    float denp = 0.f;

    float r[4], dg[4];
    #pragma unroll
    for (int j = 0; j < 4; j++) {
        int n = n0 + j;
        r[j]  = (n < n1) ? src[(size_t)n * stride] : 0.f;
        dg[j] = (t >= 192 && n < n1) ? __ldg(g_deg + n) : 0.f;
    }

    int pi = 0;
    for (int g = n0; g < n1; g += 4) {
        #pragma unroll
        for (int j = 0; j < 4; j++) vv[pi][j][t] = r[j];
        if (t >= 192) {
            #pragma unroll
            for (int j = 0; j < 4; j++) denp += dg[j] * r[j] * r[j];
        }
        // prefetch next group
        float rn[4], dn[4];
        #pragma unroll
        for (int j = 0; j < 4; j++) {
            int n = g + 4 + j;
            rn[j] = (n < n1) ? src[(size_t)n * stride] : 0.f;
            dn[j] = (t >= 192 && n < n1) ? __ldg(g_deg + n) : 0.f;
        }
        __syncthreads();

        #pragma unroll
        for (int j = 0; j < 4; j++) {
            float4 s4 = *(const float4*)&vv[pi][j][192 + rg * 4];
            u64 s0 = pack2(s4.x, s4.x), s1 = pack2(s4.y, s4.y);
            u64 s2 = pack2(s4.z, s4.z), s3 = pack2(s4.w, s4.w);
            const ulonglong2* vp = (const ulonglong2*)&vv[pi][j][cg * 16];
            #pragma unroll
            for (int h = 0; h < 4; h++) {
                ulonglong2 b2v = vp[h];
                fma2(acc[0][2*h], s0, b2v.x); fma2(acc[0][2*h+1], s0, b2v.y);
                fma2(acc[1][2*h], s1, b2v.x); fma2(acc[1][2*h+1], s1, b2v.y);
                fma2(acc[2][2*h], s2, b2v.x); fma2(acc[2][2*h+1], s2, b2v.y);
                fma2(acc[3][2*h], s3, b2v.x); fma2(acc[3][2*h+1], s3, b2v.y);
            }
        }
        pi ^= 1;
        #pragma unroll
        for (int j = 0; j < 4; j++) { r[j] = rn[j]; dg[j] = dn[j]; }
    }

    float* base = g_part + (size_t)blockIdx.x * PART_STRIDE;  // 16B-aligned
    #pragma unroll
    for (int i = 0; i < 4; i++)
        #pragma unroll
        for (int j = 0; j < 8; j++) {
            float f0, f1;
            unpack2(f0, f1, acc[i][j]);
            ((float2*)(base + (rg * 4 + i) * 256 + cg * 16))[j] = make_float2(f0, f1);
        }
    redsh[t] = denp; __syncthreads();
    for (int o = 128; o; o >>= 1) { if (t < o) redsh[t] += redsh[t + o]; __syncthreads(); }
    if (t == 0) base[16384] = redsh[0];
}

// ---------------- K3r: reduce partials across blocks ----------------
__global__ void k_reduce() {
    int i = blockIdx.x * blockDim.x + threadIdx.x;
    if (i >= PART_SIZE) return;
    float s = 0.f;
    for (int b = 0; b < NB3; b++) s += g_part[(size_t)b * PART_STRIDE + i];
    g_red[i] = s;
}

// ---------------- K4m: mc1, o1, edge pruning -> M (all from smem) ----------------
__global__ void k_small1(float* __restrict__ out) {
    __shared__ float sadj[64 * 65];
    __shared__ float ssts[64 * 65];
    __shared__ float red[256];
    __shared__ float dsi[64];
    int t = threadIdx.x;
    // stage pooled_adj block and sTs block (padded stride 65)
    for (int i = t; i < 4096; i += 256) {
        int c = i >> 6, j = i & 63;
        sadj[c * 65 + j] = g_red[c * 256 + 128 + j];
        ssts[c * 65 + j] = g_red[c * 256 + 192 + j];
    }
    __syncthreads();
    // ||sTs||_F
    float p = 0.f;
    #pragma unroll 4
    for (int i = t; i < 4096; i += 256) {
        float v = ssts[(i >> 6) * 65 + (i & 63)];
        p += v * v;
    }
    red[t] = p; __syncthreads();
    for (int o = 128; o; o >>= 1) { if (t < o) red[t] += red[t + o]; __syncthreads(); }
    float nrm = sqrtf(red[0]); __syncthreads();
    // o1
    float q = 0.f;
    #pragma unroll 4
    for (int i = t; i < 4096; i += 256) {
        int c = i >> 6, j = i & 63;
        float v = ssts[c * 65 + j] / (nrm + 1e-10f) - ((c == j) ? 0.125f : 0.f);
        q += v * v;
    }
    red[t] = q; __syncthreads();
    for (int o = 128; o; o >>= 1) { if (t < o) red[t] += red[t + o]; __syncthreads(); }
    float o1 = sqrtf(red[0]); __syncthreads();
    // trace(pooled_adj)
    float tp = (t < 64) ? sadj[t * 65 + t] : 0.f;
    red[t] = tp; __syncthreads();
    for (int o = 128; o; o >>= 1) { if (t < o) red[t] += red[t + o]; __syncthreads(); }
    if (t == 0) {
        float den = g_red[16384];
        out[0] = -red[0] / (den + 1e-10f);
        out[1] = o1;
    }
    __syncthreads();
    // degree-normalize pruned adjacency
    if (t < 64) {
        float rs = 0.f;
        #pragma unroll
        for (int j = 0; j < 64; j++) if (j != t) rs += sadj[t * 65 + j];
        dsi[t] = 1.f / (sqrtf(rs) + 1e-15f);
    }
    __syncthreads();
    for (int i = t; i < 4096; i += 256) {
        int c = i >> 6, j = i & 63;
        float a = (c == j) ? 0.f : (sadj[c * 65 + j] * dsi[c] * dsi[j]);
        g_M[i] = (a > (1.0f / 63.0f)) ? 1.f : 0.f;
    }
}

// ---------------- K4a: pooled GraphConv + LN + softmax/log_softmax ----------------
// W2rel/W2root staged transposed (padded) in smem: coalesced gmem, conflict-free LDS
#define L2_SMEM_FLOATS (16512*2 + 2048 + 128*4 + 16*2 + 64)

__global__ void k_layer2(const float* __restrict__ W2rel, const float* __restrict__ b2,
                         const float* __restrict__ W2root,
                         const float* __restrict__ pW2, const float* __restrict__ pb2,
                         const float* __restrict__ g2, const float* __restrict__ be2,
                         float* __restrict__ out) {
    extern __shared__ float sm2[];
    float* w2a  = sm2;               // [128 k][129] transposed W2rel
    float* w2b  = w2a + 16512;       // transposed W2root
    float* pws  = w2b + 16512;       // pW2 linear [16][128]
    float* ag   = pws + 2048;
    float* pr   = ag + 128;
    float* x2r  = pr + 128;
    float* praw = x2r + 128;
    float* r16  = praw + 128;
    float* v16  = r16 + 16;
    float* Mcol = v16 + 16;
    int c = blockIdx.x;     // 0..63
    int t = threadIdx.x;    // 0..127

    for (int i = t; i < 16384; i += 128) {
        int o = i >> 7, k = i & 127;
        w2a[k * 129 + o] = W2rel[i];
        w2b[k * 129 + o] = W2root[i];
    }
    for (int i = t; i < 2048; i += 128) pws[i] = pW2[i];
    if (t < 64) Mcol[t] = g_M[t * 64 + c];          // M[c'][c]
    pr[t] = g_red[c * 256 + t];                      // pooled_x[c][t]
    __syncthreads();

    float a = 0.f;
    #pragma unroll 16
    for (int cp = 0; cp < 64; cp++) a += Mcol[cp] * g_red[cp * 256 + t];
    ag[t] = a;
    __syncthreads();

    float acc = __ldg(b2 + t);
    #pragma unroll 8
    for (int k = 0; k < 128; k++)
        acc += ag[k] * w2a[k * 129 + t] + pr[k] * w2b[k * 129 + t];
    acc = fmaxf(acc, 0.f);
    x2r[t] = acc;
    __syncthreads();
    {
        int j2 = t >> 3, seg = t & 7;
        float p = 0.f;
        #pragma unroll
        for (int k = seg; k < 128; k += 8) p += x2r[k] * pws[j2 * 128 + k];
        praw[t] = p;
    }
    __syncthreads();
    if (t < 16) {
        float raw = pb2[t];
        #pragma unroll
        for (int s = 0; s < 8; s++) raw += praw[t * 8 + s];
        r16[t] = raw;
    }
    __syncthreads();
    if (t < 16) {
        float mu = 0.f, sq = 0.f;
        #pragma unroll
        for (int j = 0; j < 16; j++) { mu += r16[j]; sq += r16[j] * r16[j]; }
        mu *= (1.f / 16.f);
        float var = sq * (1.f / 16.f) - mu * mu;
        v16[t] = (r16[t] - mu) * rsqrtf(var + 1e-5f) * g2[t] + be2[t];
    }
    __syncthreads();
    if (t < 16) {
        float mx = -1e30f;
        #pragma unroll
        for (int j = 0; j < 16; j++) mx = fmaxf(mx, v16[j]);
        float se = 0.f;
        #pragma unroll
        for (int j = 0; j < 16; j++) se += __expf(v16[j] - mx);
        float e = __expf(v16[t] - mx);
        out[4 + NN * 64 + c * 16 + t] = v16[t] - mx - __logf(se);
        g_s2[c * 16 + t] = e / se;
    }
}

// ---------------- K4b: dense mincut on pooled graph -> mc2, o2 (M staged in smem) ----------------
__global__ void k_small2(float* __restrict__ out) {
    __shared__ float sM[64 * 65];
    __shared__ float s2s[NC1 * NC2];
    __shared__ float As2[NC1 * NC2];
    __shared__ float padj[NC2 * NC2];
    __shared__ float sTs[NC2 * NC2];
    __shared__ float red[256];
    int t = threadIdx.x;   // 256
    for (int i = t; i < 4096; i += 256) sM[(i >> 6) * 65 + (i & 63)] = g_M[i];
    for (int i = t; i < 1024; i += 256) s2s[i] = g_s2[i];
    __syncthreads();
    for (int i = t; i < 1024; i += 256) {
        int c = i >> 4, j = i & 15;
        float a = 0.f;
        #pragma unroll 16
        for (int cp = 0; cp < 64; cp++) a += sM[c * 65 + cp] * s2s[cp * 16 + j];
        As2[i] = a;
    }
    __syncthreads();
    {
        int aI = t >> 4, bI = t & 15;
        float pa = 0.f, st = 0.f;
        #pragma unroll 16
        for (int c = 0; c < 64; c++) {
            float sa = s2s[c * 16 + aI];
            pa += sa * As2[c * 16 + bI];
            st += sa * s2s[c * 16 + bI];
        }
        padj[t] = pa; sTs[t] = st;
    }
    __syncthreads();
    float dp = 0.f;
    if (t < 64) {
        float d = 0.f;
        #pragma unroll
        for (int j = 0; j < 64; j++) d += sM[t * 65 + j];
        float accv = 0.f;
        #pragma unroll
        for (int j = 0; j < 16; j++) { float s = s2s[t * 16 + j]; accv += s * s; }
        dp = d * accv;
    }
    red[t] = dp; __syncthreads();
    for (int o = 128; o; o >>= 1) { if (t < o) red[t] += red[t + o]; __syncthreads(); }
    float den2 = red[0]; __syncthreads();
    float trp = (t < 16) ? padj[t * 16 + t] : 0.f;
    red[t] = trp; __syncthreads();
    for (int o = 128; o; o >>= 1) { if (t < o) red[t] += red[t + o]; __syncthreads(); }
    float tr2 = red[0]; __syncthreads();
    float np = sTs[t] * sTs[t];
    red[t] = np; __syncthreads();
    for (int o = 128; o; o >>= 1) { if (t < o) red[t] += red[t + o]; __syncthreads(); }
    float norm2 = sqrtf(red[0]); __syncthreads();
    float diff = sTs[t] / (norm2 + 1e-10f) - (((t >> 4) == (t & 15)) ? 0.25f : 0.f);
    red[t] = diff * diff; __syncthreads();
    for (int o = 128; o; o >>= 1) { if (t < o) red[t] += red[t + o]; __syncthreads(); }
    if (t == 0) {
        out[2] = -tr2 / (den2 + 1e-10f);
        out[3] = sqrtf(red[0]);
    }
}

// ---------------- launch ----------------
extern "C" void kernel_launch(void* const* d_in, const int* in_sizes, int n_in,
                              void* d_out, int out_size) {
    const float* x     = (const float*)d_in[0];
    const int*   ei    = (const int*)d_in[1];
    const float* mask  = (const float*)d_in[2];
    const float* W1rel = (const float*)d_in[3];
    const float* b1    = (const float*)d_in[4];
    const float* W1rt  = (const float*)d_in[5];
    const float* pW1   = (const float*)d_in[6];
    const float* pb1   = (const float*)d_in[7];
    const float* g1    = (const float*)d_in[8];
    const float* be1   = (const float*)d_in[9];
    const float* W2rel = (const float*)d_in[10];
    const float* b2    = (const float*)d_in[11];
    const float* W2rt  = (const float*)d_in[12];
    const float* pW2   = (const float*)d_in[13];
    const float* pb2   = (const float*)d_in[14];
    const float* g2    = (const float*)d_in[15];
    const float* be2   = (const float*)d_in[16];
    float* out = (float*)d_out;
    const int* row = ei;
    const int* col = ei + EE;

    cudaFuncSetAttribute(k_node, cudaFuncAttributeMaxDynamicSharedMemorySize,
                         K2_SMEM_FLOATS * (int)sizeof(float));
    cudaFuncSetAttribute(k_layer2, cudaFuncAttributeMaxDynamicSharedMemorySize,
                         L2_SMEM_FLOATS * (int)sizeof(float));

    k_zero<<<(NN * INC / 4 + 255) / 256, 256>>>();
    k_scatter_agg<<<(EE * 16) / 256, 256>>>(x, row, col, mask);
    k_node<<<148, K2_THREADS, K2_SMEM_FLOATS * sizeof(float)>>>(
        x, mask, W1rel, b1, W1rt, pW1, pb1, g1, be1, out);
    k_scatter_As<<<(EE * 16) / 256, 256>>>(row, col);
    k_pool<<<NB3, 256>>>();
    k_reduce<<<(PART_SIZE + 255) / 256, 256>>>();
    k_small1<<<1, 256>>>(out);
    k_layer2<<<64, 128, L2_SMEM_FLOATS * sizeof(float)>>>(W2rel, b2, W2rt, pW2, pb2, g2, be2, out);
    k_small2<<<1, 256>>>(out);
}